// round 2
// baseline (speedup 1.0000x reference)
#include <cuda_runtime.h>
#include <cuda_bf16.h>
#include <math.h>

// B=8, D=64, T=512, O=256 (fixed by the reference)
#define PB 8
#define PD 64
#define PT 512
#define PO 256
#define THREADS 128

__device__ __forceinline__ float ex2a(float x) {
    float y; asm("ex2.approx.ftz.f32 %0, %1;" : "=f"(y) : "f"(x)); return y;
}
__device__ __forceinline__ float lg2a(float x) {
    float y; asm("lg2.approx.ftz.f32 %0, %1;" : "=f"(y) : "f"(x)); return y;
}

__global__ __launch_bounds__(THREADS, 8)
void interp_kernel(const float* __restrict__ x,
                   const float* __restrict__ grid,
                   const float* __restrict__ kern,
                   float* __restrict__ out) {
    // 1024 blocks: (b, d, half-of-o). 128 threads, one o each.
    const int bid  = blockIdx.x;
    const int h    = bid & 1;
    const int d    = (bid >> 1) & (PD - 1);
    const int b    = bid >> 7;
    const int tid  = threadIdx.x;
    const int lane = tid & 31;
    const int wid  = tid >> 5;

    // Compacted active points: {A, B, C, v} per active t.
    __shared__ __align__(16) float4 comp[PT + 8];
    __shared__ int warp_tot[4];
    __shared__ int s_base;

    const float* vp = x + (size_t)(b * 3 * PD + d) * PT;
    const float* mp = x + (size_t)(b * 3 * PD + PD + d) * PT;
    const float* tp = x + (size_t)(b * 3 * PD + 2 * PD + d) * PT;

    const float k = kern[d];
    const float alpha = (k > 20.0f) ? k : log1pf(__expf(k));
    const float c1 = -alpha * 1.4426950408889634f;   // -alpha*log2(e)

    if (tid == 0) s_base = 0;
    __syncthreads();

    // Block-level stream compaction of active t (mask > 0), order-preserving.
    for (int c = 0; c < PT; c += THREADS) {
        const int t = c + tid;
        const float mv = mp[t];
        const bool act = (mv > 1e-12f);
        const unsigned bal = __ballot_sync(0xffffffffu, act);
        const int pre = __popc(bal & ((1u << lane) - 1u));
        if (lane == 0) warp_tot[wid] = __popc(bal);
        __syncthreads();
        int off = s_base;
        #pragma unroll
        for (int w = 0; w < 4; w++)
            if (w < wid) off += warp_tot[w];
        if (act) {
            const float tv = tp[t];
            const float vv = vp[t];
            const float l  = (mv == 1.0f) ? 0.0f : lg2a(mv);  // log2(m)
            const float A  = __fmaf_rn(c1 * tv, tv, l);       // c1*t^2 + l
            const float Bc = -2.0f * c1 * tv;                 // -2*c1*t
            const float Cc = -9.0f * l;
            comp[off + pre] = make_float4(A, Bc, Cc, vv);
        }
        __syncthreads();
        if (tid == 0)
            s_base += warp_tot[0] + warp_tot[1] + warp_tot[2] + warp_tot[3];
        __syncthreads();
    }

    const int n = s_base;
    const int npad = (n + 7) & ~7;
    // Pad to a multiple of 8 with zero-weight entries (2^-160 flushes to 0).
    for (int i = n + tid; i < npad; i += THREADS)
        comp[i] = make_float4(-160.0f, 0.0f, 0.0f, 0.0f);
    __syncthreads();

    const int o = h * THREADS + tid;
    const float g = grid[b * PO + o];

    float aw1 = 0.f, ay1 = 0.f, aw2 = 0.f, ay2 = 0.f;

    #pragma unroll 8
    for (int i = 0; i < npad; i++) {
        const float4 e = comp[i];                       // broadcast LDS.128
        const float arg1 = __fmaf_rn(e.y, g, e.x);      // c1*t^2 - 2*c1*t*g + l
        const float e1 = ex2a(arg1);
        const float e2 = ex2a(__fmaf_rn(arg1, 10.f, e.z));
        aw1 += e1;
        ay1 = __fmaf_rn(e1, e.w, ay1);
        aw2 += e2;
        ay2 = __fmaf_rn(e2, e.w, ay2);
    }

    // Restore the per-thread constant c1*g^2 for the logsumexp output.
    const float cg2 = c1 * g * g;
    const float w = (lg2a(aw1) + cg2) * 0.6931471805599453f;

    float* ob = out + (size_t)(b * 3 * PD) * PO + o;
    ob[(size_t)(d) * PO]          = __fdividef(ay1, aw1);  // y
    ob[(size_t)(PD + d) * PO]     = w;                     // w (logsumexp)
    ob[(size_t)(2 * PD + d) * PO] = __fdividef(ay2, aw2);  // y_trans
}

extern "C" void kernel_launch(void* const* d_in, const int* in_sizes, int n_in,
                              void* d_out, int out_size) {
    const float* x    = (const float*)d_in[0];   // (8, 192, 512)
    const float* grid = (const float*)d_in[1];   // (8, 256)
    const float* kern = (const float*)d_in[2];   // (64,)
    float* out = (float*)d_out;                  // (8, 192, 256)

    interp_kernel<<<PB * PD * 2, THREADS>>>(x, grid, kern, out);
}

// round 3
// speedup vs baseline: 1.5517x; 1.5517x over previous
#include <cuda_runtime.h>
#include <cuda_bf16.h>
#include <math.h>

// B=8, D=64, T=512, O=256 (fixed by the reference)
#define PB 8
#define PD 64
#define PT 512
#define PO 256
#define THREADS 128

typedef unsigned long long u64;

__device__ __forceinline__ float ex2a(float x) {
    float y; asm("ex2.approx.ftz.f32 %0, %1;" : "=f"(y) : "f"(x)); return y;
}
__device__ __forceinline__ float lg2a(float x) {
    float y; asm("lg2.approx.ftz.f32 %0, %1;" : "=f"(y) : "f"(x)); return y;
}
__device__ __forceinline__ u64 pk2(float lo, float hi) {
    u64 r; asm("mov.b64 %0, {%1, %2};" : "=l"(r) : "f"(lo), "f"(hi)); return r;
}
__device__ __forceinline__ void upk2(u64 v, float& lo, float& hi) {
    asm("mov.b64 {%0, %1}, %2;" : "=f"(lo), "=f"(hi) : "l"(v));
}
__device__ __forceinline__ u64 fma2(u64 a, u64 b, u64 c) {
    u64 d; asm("fma.rn.f32x2 %0, %1, %2, %3;" : "=l"(d) : "l"(a), "l"(b), "l"(c)); return d;
}
__device__ __forceinline__ u64 mul2(u64 a, u64 b) {
    u64 d; asm("mul.rn.f32x2 %0, %1, %2;" : "=l"(d) : "l"(a), "l"(b)); return d;
}
__device__ __forceinline__ u64 add2(u64 a, u64 b) {
    u64 d; asm("add.rn.f32x2 %0, %1, %2;" : "=l"(d) : "l"(a), "l"(b)); return d;
}

__global__ __launch_bounds__(THREADS, 8)
void interp_kernel(const float* __restrict__ x,
                   const float* __restrict__ grid,
                   const float* __restrict__ kern,
                   float* __restrict__ out) {
    // 1024 blocks: (b, d, half-of-o). 128 threads, one o each.
    const int bid  = blockIdx.x;
    const int h    = bid & 1;
    const int d    = (bid >> 1) & (PD - 1);
    const int b    = bid >> 7;
    const int tid  = threadIdx.x;
    const int lane = tid & 31;
    const int wid  = tid >> 5;

    // Per-warp compacted segments (warp w owns t in [128w, 128w+128)).
    __shared__ __align__(16) float sA[PT];  // c1*t^2
    __shared__ __align__(16) float sB[PT];  // -2*c1*t
    __shared__ __align__(16) float sV[PT];  // vals
    __shared__ int scnt[4];                 // padded count per segment

    const float* vp = x + (size_t)(b * 3 * PD + d) * PT;
    const float* mp = x + (size_t)(b * 3 * PD + PD + d) * PT;
    const float* tp = x + (size_t)(b * 3 * PD + 2 * PD + d) * PT;

    const float k = kern[d];
    const float alpha = (k > 20.0f) ? k : log1pf(__expf(k));
    const float c1 = -alpha * 1.4426950408889634f;   // -alpha*log2(e)

    // ---- Warp-private compaction: active points have m == 1 exactly ----
    {
        const int tbase = wid * 128;
        int cnt = 0;
        #pragma unroll
        for (int r = 0; r < 4; r++) {
            const int t = tbase + r * 32 + lane;
            const float mv = mp[t];
            const float tv = tp[t];
            const float vv = vp[t];
            const bool act = (mv > 0.5f);
            const unsigned bal = __ballot_sync(0xffffffffu, act);
            if (act) {
                const int idx = tbase + cnt + __popc(bal & ((1u << lane) - 1u));
                sA[idx] = c1 * tv * tv;
                sB[idx] = -2.0f * c1 * tv;
                sV[idx] = vv;
            }
            cnt += __popc(bal);
        }
        const int cpad = (cnt + 7) & ~7;   // <= 128 always
        for (int i = cnt + lane; i < cpad; i += 32) {
            sA[tbase + i] = -160.0f;       // 2^-160 -> FTZ 0: zero weight
            sB[tbase + i] = 0.0f;
            sV[tbase + i] = 0.0f;
        }
        if (lane == 0) scnt[wid] = cpad;
    }
    __syncthreads();

    const int o = h * THREADS + tid;
    const float g = grid[b * PO + o];
    const u64 gg = pk2(g, g);

    u64 aw1 = 0, ay1 = 0, aw2 = 0, ay2 = 0;

    #pragma unroll
    for (int seg = 0; seg < 4; seg++) {
        const int base = seg * 128;
        const int ns = scnt[seg];
        for (int i = 0; i < ns; i += 8) {
            #pragma unroll
            for (int p = 0; p < 4; p++) {
                const int idx = base + i + 2 * p;
                const u64 Ap = *(const u64*)(sA + idx);   // (A0,A1) packed
                const u64 Bp = *(const u64*)(sB + idx);
                const u64 Vp = *(const u64*)(sV + idx);
                const u64 arg = fma2(Bp, gg, Ap);         // c1(t-g)^2 - c1 g^2
                float a0, a1; upk2(arg, a0, a1);
                const u64 E1 = pk2(ex2a(a0), ex2a(a1));
                const u64 s2 = mul2(E1, E1);
                const u64 s4 = mul2(s2, s2);
                const u64 s8 = mul2(s4, s4);
                const u64 E2 = mul2(s8, s2);              // e1^10 (logm == 0)
                aw1 = add2(aw1, E1);
                ay1 = fma2(E1, Vp, ay1);
                aw2 = add2(aw2, E2);
                ay2 = fma2(E2, Vp, ay2);
            }
        }
    }

    float w1l, w1h, y1l, y1h, w2l, w2h, y2l, y2h;
    upk2(aw1, w1l, w1h); upk2(ay1, y1l, y1h);
    upk2(aw2, w2l, w2h); upk2(ay2, y2l, y2h);
    const float sw1 = w1l + w1h;
    const float sy1 = y1l + y1h;
    const float sw2 = w2l + w2h;
    const float sy2 = y2l + y2h;

    // Restore per-thread constant c1*g^2 for the logsumexp output.
    const float cg2 = c1 * g * g;
    const float w = (lg2a(sw1) + cg2) * 0.6931471805599453f;

    float* ob = out + (size_t)(b * 3 * PD) * PO + o;
    ob[(size_t)(d) * PO]          = __fdividef(sy1, sw1);  // y
    ob[(size_t)(PD + d) * PO]     = w;                     // w (logsumexp)
    ob[(size_t)(2 * PD + d) * PO] = __fdividef(sy2, sw2);  // y_trans
}

extern "C" void kernel_launch(void* const* d_in, const int* in_sizes, int n_in,
                              void* d_out, int out_size) {
    const float* x    = (const float*)d_in[0];   // (8, 192, 512)
    const float* grid = (const float*)d_in[1];   // (8, 256)
    const float* kern = (const float*)d_in[2];   // (64,)
    float* out = (float*)d_out;                  // (8, 192, 256)

    interp_kernel<<<PB * PD * 2, THREADS>>>(x, grid, kern, out);
}